// round 17
// baseline (speedup 1.0000x reference)
#include <cuda_runtime.h>
#include <cuda_fp16.h>
#include <cstdint>

// ---------------------------------------------------------------------------
// Problem constants: B=2048, T=2, N(tokens)=64, C=256, H=8, hd=32
// ---------------------------------------------------------------------------
#define B_SZ   2048
#define T_SZ   2
#define NTOK   64
#define CDIM   256
#define NHEAD  8
#define HDIM   32

#define QK_SCALE 0.17677669529663687f   // 1/sqrt(32)
#define EROWS   20                      // fma-pipe rows per GEMM block

// Scratch (allocation-free contract: __device__ globals) — all fp16
__device__ __half g_qh  [33554432];   // (B*N, C)     q projection * scale
__device__ __half g_kvh [134217728];  // (B*T*N, 2C)  kv projection
__device__ __half g_atth[67108864];   // (B*T*N, C)   attention output
__device__ float  g_bias[32768];      // (H, N, N)

// ---------------------------------------------------------------------------
// Helpers
// ---------------------------------------------------------------------------
__device__ __forceinline__ void mma_f16(float (&d)[4], const uint32_t (&a)[4],
                                        uint32_t b0, uint32_t b1) {
    asm volatile(
        "mma.sync.aligned.m16n8k16.row.col.f32.f16.f16.f32 "
        "{%0,%1,%2,%3}, {%4,%5,%6,%7}, {%8,%9}, {%0,%1,%2,%3};\n"
        : "+f"(d[0]), "+f"(d[1]), "+f"(d[2]), "+f"(d[3])
        : "r"(a[0]), "r"(a[1]), "r"(a[2]), "r"(a[3]), "r"(b0), "r"(b1));
}

__device__ __forceinline__ uint2 h4pack(float4 v) {
    __half2 lo = __floats2half2_rn(v.x, v.y);
    __half2 hi = __floats2half2_rn(v.z, v.w);
    uint2 u;
    u.x = *reinterpret_cast<uint32_t*>(&lo);
    u.y = *reinterpret_cast<uint32_t*>(&hi);
    return u;
}

__device__ __forceinline__ uint32_t h2bits(float a, float b) {
    __half2 h = __floats2half2_rn(a, b);
    return *reinterpret_cast<uint32_t*>(&h);
}

// ---------------------------------------------------------------------------
// Relative position bias table -> dense (H, 64, 64)
// ---------------------------------------------------------------------------
__global__ void bias_kernel(const float* __restrict__ rpb) {
    int n = blockIdx.x;    // query token
    int m = threadIdx.x;   // key token
    int in_ = n >> 3, jn = n & 7;
    int im  = m >> 3, jm = m & 7;
    int idx = (in_ - im + 7) * 15 + (jn - jm + 7);
#pragma unroll
    for (int h = 0; h < NHEAD; h++)
        g_bias[h * 4096 + n * 64 + m] = rpb[idx * NHEAD + h];
}

// ---------------------------------------------------------------------------
// Hybrid GEMM block: 128 rows via fp16 HMMA  +  EROWS extra rows via fp32
// FFMA (fma pipe runs in the tensor unit's shadow).
// C[M,N] = (A[M,256] * W[N,256]^T + bias[N]) * outScale
// 256 threads = 8 warps (2m x 4n), HMMA warp tile 64x32, BK=32.
// Extra-row ownership: cg = tid&127 -> col, rg = tid>>7 -> rows rg*10..+9.
// ---------------------------------------------------------------------------
template <int N, bool AHALF, bool OHALF>
__device__ __forceinline__ void gemm_core(const void* __restrict__ Av,
                                          const float* __restrict__ W,
                                          const float* __restrict__ bias,
                                          void* __restrict__ Cv,
                                          float outScale,
                                          long long Mtotal,
                                          long long hRowBase,
                                          long long eRowBase) {
    constexpr int K = 256;
    __shared__ __align__(16) __half As[128][40];   // HMMA A tile (fp16)
    __shared__ __align__(16) __half Bs[128][40];   // W tile (fp16)
    __shared__ __align__(16) float  Ae[32][EROWS]; // extra rows, k-major fp32

    const float*  Af = (const float*)Av;
    const __half* Ah = (const __half*)Av;

    const int tid  = threadIdx.x;
    const int lane = tid & 31;
    const int warp = tid >> 5;
    const int wm = warp & 1, wn = warp >> 1;       // 2 x 4 warp grid
    const int tg = lane & 3, gp = lane >> 2;
    const int colBase = blockIdx.y * 128;

    const int ldr = tid >> 3;          // 0..31
    const int ldc = (tid & 7) * 4;     // 4-element col within 32-wide k-tile

    // extra-row staging assignment (threads < 160): er 0..19, ec4 {0,4,..,28}
    const int er  = tid >> 3;
    const int ec4 = (tid & 7) * 4;
    const bool eStage = (tid < 160);
    const long long egRow = eRowBase + er;
    const bool eValid = eStage && (egRow < Mtotal);

    // extra-row compute assignment
    const int cg = tid & 127;          // col within tile
    const int rg = tid >> 7;           // 0..1 -> rows rg*10..rg*10+9

    float4 paf[4];
    uint2  pah[4];
    float4 pb[4];
    float4 pef;
    uint2  peh;

    // prefetch kt = 0
#pragma unroll
    for (int i = 0; i < 4; i++) {
        int r = ldr + i * 32;
        if (AHALF) pah[i] = *(const uint2*)(Ah + (hRowBase + r) * K + ldc);
        else       paf[i] = *(const float4*)(Af + (hRowBase + r) * K + ldc);
        pb[i] = *(const float4*)(W + (long long)(colBase + r) * K + ldc);
    }
    if (eValid) {
        if (AHALF) peh = *(const uint2*)(Ah + egRow * K + ec4);
        else       pef = *(const float4*)(Af + egRow * K + ec4);
    }

    float acc[4][4][4];
#pragma unroll
    for (int mt = 0; mt < 4; mt++)
#pragma unroll
        for (int nt = 0; nt < 4; nt++)
#pragma unroll
            for (int i = 0; i < 4; i++) acc[mt][nt][i] = 0.0f;

    float accE[10];
#pragma unroll
    for (int i = 0; i < 10; i++) accE[i] = 0.0f;

#pragma unroll 1
    for (int kt = 0; kt < K; kt += 32) {
        // stage -> smem
#pragma unroll
        for (int i = 0; i < 4; i++) {
            int r = ldr + i * 32;
            *(uint2*)&As[r][ldc] = AHALF ? pah[i] : h4pack(paf[i]);
            *(uint2*)&Bs[r][ldc] = h4pack(pb[i]);
        }
        if (eStage) {
            if (eValid) {
                if (AHALF) {
                    __half hh[4];
                    *(uint2*)hh = peh;
                    Ae[ec4 + 0][er] = __half2float(hh[0]);
                    Ae[ec4 + 1][er] = __half2float(hh[1]);
                    Ae[ec4 + 2][er] = __half2float(hh[2]);
                    Ae[ec4 + 3][er] = __half2float(hh[3]);
                } else {
                    Ae[ec4 + 0][er] = pef.x;
                    Ae[ec4 + 1][er] = pef.y;
                    Ae[ec4 + 2][er] = pef.z;
                    Ae[ec4 + 3][er] = pef.w;
                }
            } else {
                Ae[ec4 + 0][er] = 0.0f;
                Ae[ec4 + 1][er] = 0.0f;
                Ae[ec4 + 2][er] = 0.0f;
                Ae[ec4 + 3][er] = 0.0f;
            }
        }
        __syncthreads();

        // prefetch next tile while computing
        if (kt + 32 < K) {
            const int ktn = kt + 32;
#pragma unroll
            for (int i = 0; i < 4; i++) {
                int r = ldr + i * 32;
                if (AHALF) pah[i] = *(const uint2*)(Ah + (hRowBase + r) * K + ktn + ldc);
                else       paf[i] = *(const float4*)(Af + (hRowBase + r) * K + ktn + ldc);
                pb[i] = *(const float4*)(W + (long long)(colBase + r) * K + ktn + ldc);
            }
            if (eValid) {
                if (AHALF) peh = *(const uint2*)(Ah + egRow * K + ktn + ec4);
                else       pef = *(const float4*)(Af + egRow * K + ktn + ec4);
            }
        }

        // ---- HMMA path: 128 rows ----
#pragma unroll
        for (int kk = 0; kk < 32; kk += 16) {
            uint32_t a[4][4];
#pragma unroll
            for (int mt = 0; mt < 4; mt++) {
                int r0 = wm * 64 + mt * 16 + gp;
                a[mt][0] = *(const uint32_t*)&As[r0][kk + tg * 2];
                a[mt][1] = *(const uint32_t*)&As[r0 + 8][kk + tg * 2];
                a[mt][2] = *(const uint32_t*)&As[r0][kk + tg * 2 + 8];
                a[mt][3] = *(const uint32_t*)&As[r0 + 8][kk + tg * 2 + 8];
            }
#pragma unroll
            for (int nt = 0; nt < 4; nt++) {
                int c0 = wn * 32 + nt * 8 + gp;
                uint32_t b0 = *(const uint32_t*)&Bs[c0][kk + tg * 2];
                uint32_t b1 = *(const uint32_t*)&Bs[c0][kk + tg * 2 + 8];
#pragma unroll
                for (int mt = 0; mt < 4; mt++)
                    mma_f16(acc[mt][nt], a[mt], b0, b1);
            }
        }

        // ---- FFMA path: EROWS extra rows (fma pipe, tensor shadow) ----
        {
            const int rb = rg * 10;
#pragma unroll
            for (int k = 0; k < 32; k++) {
                float bv = __half2float(Bs[cg][k]);
                float2 a0 = *(const float2*)&Ae[k][rb];
                float2 a1 = *(const float2*)&Ae[k][rb + 2];
                float2 a2 = *(const float2*)&Ae[k][rb + 4];
                float2 a3 = *(const float2*)&Ae[k][rb + 6];
                float2 a4 = *(const float2*)&Ae[k][rb + 8];
                accE[0] += a0.x * bv;  accE[1] += a0.y * bv;
                accE[2] += a1.x * bv;  accE[3] += a1.y * bv;
                accE[4] += a2.x * bv;  accE[5] += a2.y * bv;
                accE[6] += a3.x * bv;  accE[7] += a3.y * bv;
                accE[8] += a4.x * bv;  accE[9] += a4.y * bv;
            }
        }
        __syncthreads();
    }

    // epilogue: HMMA rows
#pragma unroll
    for (int mt = 0; mt < 4; mt++) {
        long long r0 = hRowBase + wm * 64 + mt * 16 + gp;
#pragma unroll
        for (int nt = 0; nt < 4; nt++) {
            int c0 = colBase + wn * 32 + nt * 8 + tg * 2;
            float b0 = __ldg(bias + c0), b1 = __ldg(bias + c0 + 1);
            float v0 = (acc[mt][nt][0] + b0) * outScale;
            float v1 = (acc[mt][nt][1] + b1) * outScale;
            float v2 = (acc[mt][nt][2] + b0) * outScale;
            float v3 = (acc[mt][nt][3] + b1) * outScale;
            if (OHALF) {
                __half* C = (__half*)Cv;
                *(uint32_t*)(C + r0 * N + c0)       = h2bits(v0, v1);
                *(uint32_t*)(C + (r0 + 8) * N + c0) = h2bits(v2, v3);
            } else {
                float* C = (float*)Cv;
                *(float2*)(C + r0 * N + c0)       = make_float2(v0, v1);
                *(float2*)(C + (r0 + 8) * N + c0) = make_float2(v2, v3);
            }
        }
    }

    // epilogue: extra rows (guarded)
    {
        int c = colBase + cg;
        float bc = __ldg(bias + c);
#pragma unroll
        for (int i = 0; i < 10; i++) {
            long long gr = eRowBase + rg * 10 + i;
            if (gr < Mtotal) {
                float v = (accE[i] + bc) * outScale;
                if (OHALF) ((__half*)Cv)[gr * N + c] = __float2half_rn(v);
                else       ((float*)Cv)[gr * N + c] = v;
            }
        }
    }
}

__global__ __launch_bounds__(256, 2) void gemm_q_kernel(const float* __restrict__ A,
                                                        const float* __restrict__ W,
                                                        const float* __restrict__ bias) {
    const long long MH = 896LL * 128;   // 114688
    gemm_core<256, false, true>(A, W, bias, g_qh, QK_SCALE,
                                131072LL, (long long)blockIdx.x * 128,
                                MH + (long long)blockIdx.x * EROWS);
}
__global__ __launch_bounds__(256, 2) void gemm_kv_kernel(const float* __restrict__ A,
                                                         const float* __restrict__ W,
                                                         const float* __restrict__ bias) {
    const long long MH = 1792LL * 128;  // 229376
    gemm_core<512, false, true>(A, W, bias, g_kvh, 1.0f,
                                262144LL, (long long)blockIdx.x * 128,
                                MH + (long long)blockIdx.x * EROWS);
}
__global__ __launch_bounds__(256, 2) void gemm_proj_kernel(const float* __restrict__ W,
                                                           const float* __restrict__ bias,
                                                           float* __restrict__ C) {
    const long long MH = 1792LL * 128;  // 229376
    gemm_core<256, true, false>(g_atth, W, bias, C, 1.0f,
                                262144LL, (long long)blockIdx.x * 128,
                                MH + (long long)blockIdx.x * EROWS);
}

// ---------------------------------------------------------------------------
// Fused attention (unchanged from R16 winner): one block per (b, h), 2 warps,
// t-loop, P fragments in registers via QK-C == PV-A layout identity.
// ---------------------------------------------------------------------------
#define QS(r, c)  smh[(r) * 40 + (c)]
#define KS(r, c)  smh[2560 + (r) * 40 + (c)]
#define VT(n, k)  smh[5120 + (n) * 72 + (k)]

__global__ __launch_bounds__(64) void attn_kernel() {
    __shared__ __align__(16) __half smh[7424];   // 14848 B

    const int bid = blockIdx.x;
    const int h = bid & 7;
    const int b = bid >> 3;
    const int tid = threadIdx.x;
    const int warp = tid >> 5, lane = tid & 31;
    const int tg = lane & 3, gp = lane >> 2;
    const int row0 = warp * 32;
    const float* bh = g_bias + h * 4096;

    const __half* qptr = g_qh + ((long long)b * NTOK) * CDIM + h * HDIM;

#pragma unroll
    for (int i = 0; i < 4; i++) {
        int idx = tid + i * 64;
        int r = idx >> 2, c = (idx & 3) * 8;
        *(uint4*)&QS(r, c) = *(const uint4*)(qptr + (long long)r * CDIM + c);
    }

#pragma unroll 1
    for (int t = 0; t < T_SZ; t++) {
        const __half* kptr = g_kvh + (((long long)b * T_SZ + t) * NTOK) * (2 * CDIM) + h * HDIM;
        const __half* vptr = kptr + CDIM;

#pragma unroll
        for (int i = 0; i < 4; i++) {
            int idx = tid + i * 64;
            int r = idx >> 2, c = (idx & 3) * 8;
            *(uint4*)&KS(r, c) = *(const uint4*)(kptr + (long long)r * (2 * CDIM) + c);
            uint4 v4 = *(const uint4*)(vptr + (long long)r * (2 * CDIM) + c);
            __half vtmp[8];
            *(uint4*)vtmp = v4;
#pragma unroll
            for (int j = 0; j < 8; j++) VT(c + j, r) = vtmp[j];
        }
        __syncthreads();

        float s[2][8][4];
#pragma unroll
        for (int mt = 0; mt < 2; mt++)
#pragma unroll
            for (int nt = 0; nt < 8; nt++)
                s[mt][nt][0] = s[mt][nt][1] = s[mt][nt][2] = s[mt][nt][3] = 0.0f;

#pragma unroll
        for (int kk = 0; kk < HDIM; kk += 16) {
            uint32_t a[2][4];
#pragma unroll
            for (int mt = 0; mt < 2; mt++) {
                int r0 = row0 + mt * 16 + gp;
                a[mt][0] = *(const uint32_t*)&QS(r0, kk + tg * 2);
                a[mt][1] = *(const uint32_t*)&QS(r0 + 8, kk + tg * 2);
                a[mt][2] = *(const uint32_t*)&QS(r0, kk + tg * 2 + 8);
                a[mt][3] = *(const uint32_t*)&QS(r0 + 8, kk + tg * 2 + 8);
            }
#pragma unroll
            for (int nt = 0; nt < 8; nt++) {
                int m0 = nt * 8 + gp;
                uint32_t b0 = *(const uint32_t*)&KS(m0, kk + tg * 2);
                uint32_t b1 = *(const uint32_t*)&KS(m0, kk + tg * 2 + 8);
#pragma unroll
                for (int mt = 0; mt < 2; mt++)
                    mma_f16(s[mt][nt], a[mt], b0, b1);
            }
        }

        float inv[2][2];
#pragma unroll
        for (int mt = 0; mt < 2; mt++) {
            const int r1 = row0 + mt * 16 + gp, r2 = r1 + 8;
            float m1 = -1e30f, m2 = -1e30f;
#pragma unroll
            for (int nt = 0; nt < 8; nt++) {
                int c = nt * 8 + tg * 2;
                float2 bb1 = *(const float2*)(bh + r1 * 64 + c);
                float2 bb2 = *(const float2*)(bh + r2 * 64 + c);
                s[mt][nt][0] += bb1.x;  s[mt][nt][1] += bb1.y;
                s[mt][nt][2] += bb2.x;  s[mt][nt][3] += bb2.y;
                m1 = fmaxf(m1, fmaxf(s[mt][nt][0], s[mt][nt][1]));
                m2 = fmaxf(m2, fmaxf(s[mt][nt][2], s[mt][nt][3]));
            }
            m1 = fmaxf(m1, __shfl_xor_sync(0xffffffffu, m1, 1));
            m1 = fmaxf(m1, __shfl_xor_sync(0xffffffffu, m1, 2));
            m2 = fmaxf(m2, __shfl_xor_sync(0xffffffffu, m2, 1));
            m2 = fmaxf(m2, __shfl_xor_sync(0xffffffffu, m2, 2));

            float sum1 = 0.0f, sum2 = 0.0f;
#pragma unroll
            for (int nt = 0; nt < 8; nt++) {
                s[mt][nt][0] = __expf(s[mt][nt][0] - m1);
                s[mt][nt][1] = __expf(s[mt][nt][1] - m1);
                s[mt][nt][2] = __expf(s[mt][nt][2] - m2);
                s[mt][nt][3] = __expf(s[mt][nt][3] - m2);
                sum1 += s[mt][nt][0] + s[mt][nt][1];
                sum2 += s[mt][nt][2] + s[mt][nt][3];
            }
            sum1 += __shfl_xor_sync(0xffffffffu, sum1, 1);
            sum1 += __shfl_xor_sync(0xffffffffu, sum1, 2);
            sum2 += __shfl_xor_sync(0xffffffffu, sum2, 1);
            sum2 += __shfl_xor_sync(0xffffffffu, sum2, 2);
            inv[mt][0] = 1.0f / sum1;
            inv[mt][1] = 1.0f / sum2;
        }

        uint32_t ph[2][8][2];
#pragma unroll
        for (int mt = 0; mt < 2; mt++)
#pragma unroll
            for (int nt = 0; nt < 8; nt++) {
                ph[mt][nt][0] = h2bits(s[mt][nt][0] * inv[mt][0],
                                       s[mt][nt][1] * inv[mt][0]);
                ph[mt][nt][1] = h2bits(s[mt][nt][2] * inv[mt][1],
                                       s[mt][nt][3] * inv[mt][1]);
            }

        float o[2][4][4];
#pragma unroll
        for (int mt = 0; mt < 2; mt++)
#pragma unroll
            for (int nt = 0; nt < 4; nt++)
                o[mt][nt][0] = o[mt][nt][1] = o[mt][nt][2] = o[mt][nt][3] = 0.0f;

#pragma unroll
        for (int kk = 0; kk < NTOK; kk += 16) {
            const int pt = kk >> 3;
            uint32_t a[2][4];
#pragma unroll
            for (int mt = 0; mt < 2; mt++) {
                a[mt][0] = ph[mt][pt][0];
                a[mt][1] = ph[mt][pt][1];
                a[mt][2] = ph[mt][pt + 1][0];
                a[mt][3] = ph[mt][pt + 1][1];
            }
#pragma unroll
            for (int nt = 0; nt < 4; nt++) {
                int n0 = nt * 8 + gp;
                uint32_t b0 = *(const uint32_t*)&VT(n0, kk + tg * 2);
                uint32_t b1 = *(const uint32_t*)&VT(n0, kk + tg * 2 + 8);
#pragma unroll
                for (int mt = 0; mt < 2; mt++)
                    mma_f16(o[mt][nt], a[mt], b0, b1);
            }
        }

        __half* op = g_atth + (((long long)b * T_SZ + t) * NTOK) * CDIM + h * HDIM;
#pragma unroll
        for (int mt = 0; mt < 2; mt++) {
            const int r1 = row0 + mt * 16 + gp, r2 = r1 + 8;
#pragma unroll
            for (int nt = 0; nt < 4; nt++) {
                int c = nt * 8 + tg * 2;
                *(uint32_t*)(op + (long long)r1 * CDIM + c) = h2bits(o[mt][nt][0], o[mt][nt][1]);
                *(uint32_t*)(op + (long long)r2 * CDIM + c) = h2bits(o[mt][nt][2], o[mt][nt][3]);
            }
        }

        __syncthreads();
    }
}

// ---------------------------------------------------------------------------
// Launch
// ---------------------------------------------------------------------------
extern "C" void kernel_launch(void* const* d_in, const int* in_sizes, int n_in,
                              void* d_out, int out_size) {
    const float* x      = (const float*)d_in[0];
    const float* memory = (const float*)d_in[1];
    const float* q_w    = (const float*)d_in[2];
    const float* q_b    = (const float*)d_in[3];
    const float* kv_w   = (const float*)d_in[4];
    const float* kv_b   = (const float*)d_in[5];
    const float* proj_w = (const float*)d_in[6];
    const float* proj_b = (const float*)d_in[7];
    const float* rpb    = (const float*)d_in[8];
    float* out = (float*)d_out;

    // (H,64,64) dense bias table (128 KB, L2-resident)
    bias_kernel<<<64, 64>>>(rpb);

    // q projection: 896 hybrid blocks cover 114688 HMMA + 16384 FFMA rows
    gemm_q_kernel<<<dim3(896, 2), 256>>>(x, q_w, q_b);

    // kv projection: 1792 hybrid blocks cover 229376 + 32768 rows
    gemm_kv_kernel<<<dim3(1792, 4), 256>>>(memory, kv_w, kv_b);

    // fused attention: one block per (b, h), loops t
    attn_kernel<<<B_SZ * NHEAD, 64>>>();

    // output projection: same hybrid split -> fp32 d_out
    gemm_proj_kernel<<<dim3(1792, 2), 256>>>(proj_w, proj_b, out);
}